// round 1
// baseline (speedup 1.0000x reference)
#include <cuda_runtime.h>
#include <cstdint>

// Problem constants (fixed by setup_inputs)
#define Rr      128
#define Nn      256
#define Dd      128
#define Hh      8
#define DHh     64
#define INNERi  512
#define MROWS   (Rr*Nn)      // 32768
#define PW      1664         // packed proj width: 512 q | 512 k | 512 v | 128 ksw

// ---------------- scratch (static device globals; no allocation) ----------------
__device__ float g_proj [(size_t)MROWS*PW];     // 218 MB: q|k|v|ksw rows
__device__ float g_Wpack[Dd*PW];
__device__ float g_bpack[PW];
__device__ float g_qsw  [Nn*Dd];
__device__ float g_w    [Nn*Hh*Rr];             // softmaxed row weights [n][h][r]
__device__ float g_dots [2*Hh*Nn*Nn];           // two r-split partial planes
__device__ float g_bias [Nn*Nn*Hh];             // pair bias -> heads [i][j][h]
__device__ float g_attn [Hh*Nn*Nn];
__device__ float g_ypre [(size_t)MROWS*INNERi]; // 64 MB

// ---------------- weight packing: [wq | wkv | swk_w], bias = [0 | 0 | swk_b] ----
__global__ void packw_kernel(const float* __restrict__ wq,
                             const float* __restrict__ wkv,
                             const float* __restrict__ swkw,
                             const float* __restrict__ swkb)
{
    int idx = blockIdx.x*blockDim.x + threadIdx.x;
    if (idx < Dd*PW) {
        int k = idx / PW, c = idx % PW;
        float v;
        if      (c < 512)  v = wq  [k*512  + c];
        else if (c < 1536) v = wkv [k*1024 + (c-512)];
        else               v = swkw[k*Dd   + (c-1536)];
        g_Wpack[idx] = v;
    }
    if (idx < PW) g_bpack[idx] = (idx < 1536) ? 0.f : swkb[idx-1536];
}

// ---------------- generic 64x64 sgemm (row-major A[M,K] * B[K,N] + bias) --------
__global__ void __launch_bounds__(256)
sgemm_kernel(const float* __restrict__ A, const float* __restrict__ B,
             const float* __restrict__ bias, float* __restrict__ C,
             int M, int N, int K)
{
    __shared__ float As[16][68];   // transposed [k][m], padded for conflicts+align
    __shared__ float Bs[16][64];   // [k][n]
    const int t  = threadIdx.x;
    const int tx = t & 15, ty = t >> 4;
    const int n0 = blockIdx.x*64, m0 = blockIdx.y*64;
    const int arow = t >> 2, ak4 = t & 3;     // A tile: 64x16 -> 256 float4
    const int brow = t >> 4, bc4 = t & 15;    // B tile: 16x64 -> 256 float4
    float acc[4][4] = {};

    for (int k0 = 0; k0 < K; k0 += 16) {
        float4 a = *(const float4*)&A[(size_t)(m0+arow)*K + k0 + ak4*4];
        As[ak4*4+0][arow] = a.x;
        As[ak4*4+1][arow] = a.y;
        As[ak4*4+2][arow] = a.z;
        As[ak4*4+3][arow] = a.w;
        *(float4*)&Bs[brow][bc4*4] =
            *(const float4*)&B[(size_t)(k0+brow)*N + n0 + bc4*4];
        __syncthreads();
        #pragma unroll
        for (int kk = 0; kk < 16; kk++) {
            float4 ra = *(const float4*)&As[kk][ty*4];
            float4 rb = *(const float4*)&Bs[kk][tx*4];
            acc[0][0] += ra.x*rb.x; acc[0][1] += ra.x*rb.y; acc[0][2] += ra.x*rb.z; acc[0][3] += ra.x*rb.w;
            acc[1][0] += ra.y*rb.x; acc[1][1] += ra.y*rb.y; acc[1][2] += ra.y*rb.z; acc[1][3] += ra.y*rb.w;
            acc[2][0] += ra.z*rb.x; acc[2][1] += ra.z*rb.y; acc[2][2] += ra.z*rb.z; acc[2][3] += ra.z*rb.w;
            acc[3][0] += ra.w*rb.x; acc[3][1] += ra.w*rb.y; acc[3][2] += ra.w*rb.z; acc[3][3] += ra.w*rb.w;
        }
        __syncthreads();
    }
    float4 bv = make_float4(0.f,0.f,0.f,0.f);
    if (bias) bv = *(const float4*)&bias[n0 + tx*4];
    #pragma unroll
    for (int m = 0; m < 4; m++) {
        float4 o = make_float4(acc[m][0]+bv.x, acc[m][1]+bv.y,
                               acc[m][2]+bv.z, acc[m][3]+bv.w);
        *(float4*)&C[(size_t)(m0 + ty*4 + m)*N + n0 + tx*4] = o;
    }
}

// ---------------- positional seq-weight: logits + softmax over r ----------------
__global__ void __launch_bounds__(128)
seqw_kernel()
{
    const int n = blockIdx.x >> 3, h = blockIdx.x & 7;
    const int r = threadIdx.x;
    __shared__ float qs[16];
    __shared__ float red[4];
    if (r < 16) qs[r] = g_qsw[n*Dd + h*16 + r];
    __syncthreads();
    const float* kp = g_proj + ((size_t)(r*Nn + n))*PW + 1536 + h*16;
    float s = 0.f;
    #pragma unroll
    for (int d = 0; d < 16; d++) s += qs[d]*kp[d];
    s *= 0.25f;   // 1/sqrt(SWD=16)
    const int lane = r & 31, wid = r >> 5;
    float m = s;
    #pragma unroll
    for (int o = 16; o; o >>= 1) m = fmaxf(m, __shfl_xor_sync(0xffffffffu, m, o));
    if (lane == 0) red[wid] = m;
    __syncthreads();
    m = fmaxf(fmaxf(red[0],red[1]), fmaxf(red[2],red[3]));
    __syncthreads();
    float e = __expf(s - m);
    float su = e;
    #pragma unroll
    for (int o = 16; o; o >>= 1) su += __shfl_xor_sync(0xffffffffu, su, o);
    if (lane == 0) red[wid] = su;
    __syncthreads();
    su = red[0]+red[1]+red[2]+red[3];
    g_w[(n*Hh + h)*Rr + r] = e/su;
}

// ---------------- pair bias: per-(i,j) LayerNorm + Linear(128->8) --------------
__global__ void __launch_bounds__(256)
pairbias_kernel(const float* __restrict__ pb, const float* __restrict__ gg,
                const float* __restrict__ bb, const float* __restrict__ wp)
{
    __shared__ float s_wp[Dd*Hh];
    __shared__ float s_g[Dd], s_b[Dd];
    const int t = threadIdx.x;
    for (int k = t; k < Dd*Hh; k += 256) s_wp[k] = wp[k];
    if (t < Dd) { s_g[t] = gg[t]; s_b[t] = bb[t]; }
    __syncthreads();
    const int warp = t >> 5, lane = t & 31;
    const int p = blockIdx.x*8 + warp;                 // (i,j) pair index
    const float* rowp = pb + (size_t)p*Dd;
    float v[4];
    #pragma unroll
    for (int u = 0; u < 4; u++) v[u] = rowp[lane + 32*u];
    float s = v[0]+v[1]+v[2]+v[3];
    #pragma unroll
    for (int o = 16; o; o >>= 1) s += __shfl_xor_sync(0xffffffffu, s, o);
    const float mu = s * (1.f/128.f);
    float q = 0.f;
    #pragma unroll
    for (int u = 0; u < 4; u++) { float d = v[u]-mu; q += d*d; }
    #pragma unroll
    for (int o = 16; o; o >>= 1) q += __shfl_xor_sync(0xffffffffu, q, o);
    const float rstd = rsqrtf(q*(1.f/128.f) + 1e-5f);
    float acc[8] = {};
    #pragma unroll
    for (int u = 0; u < 4; u++) {
        int c = lane + 32*u;
        float ln = (v[u]-mu)*rstd*s_g[c] + s_b[c];
        #pragma unroll
        for (int h = 0; h < 8; h++) acc[h] += ln*s_wp[c*8 + h];
    }
    #pragma unroll
    for (int h = 0; h < 8; h++)
        #pragma unroll
        for (int o = 16; o; o >>= 1) acc[h] += __shfl_xor_sync(0xffffffffu, acc[h], o);
    float outv = 0.f;
    #pragma unroll
    for (int h = 0; h < 8; h++) if (lane == h) outv = acc[h];
    if (lane < 8) g_bias[(size_t)p*8 + lane] = outv;
}

// ---------------- tied dots: dots[h,i,j] = 1/8 * sum_{r,d} w[i,h,r]q[r,i,h,d]k[r,j,h,d]
// r-split=2 partial planes to double block count (128 -> 256 blocks)
__global__ void __launch_bounds__(256)
dots_kernel()
{
    __shared__ float Qs[64][68];   // [i][d]
    __shared__ float Ks[64][68];   // [j][d]
    const int t = threadIdx.x, tx = t & 15, ty = t >> 4;
    const int j0 = blockIdx.x*64, i0 = blockIdx.y*64;
    const int h = blockIdx.z >> 1, rs = blockIdx.z & 1;
    const int qc = h*64, kc = 512 + h*64;
    float acc[4][4] = {};

    for (int r = rs*64; r < rs*64 + 64; ++r) {
        #pragma unroll
        for (int u = 0; u < 4; u++) {
            int idx = u*256 + t, row = idx >> 4, c4 = idx & 15;
            float4 a = *(const float4*)(g_proj + ((size_t)(r*Nn + i0+row))*PW + qc + c4*4);
            float sc = g_w[((i0+row)*Hh + h)*Rr + r];
            a.x *= sc; a.y *= sc; a.z *= sc; a.w *= sc;
            *(float4*)&Qs[row][c4*4] = a;
            *(float4*)&Ks[row][c4*4] =
                *(const float4*)(g_proj + ((size_t)(r*Nn + j0+row))*PW + kc + c4*4);
        }
        __syncthreads();
        #pragma unroll
        for (int d4 = 0; d4 < 16; ++d4) {
            float4 qa[4], kb[4];
            #pragma unroll
            for (int m = 0; m < 4; m++)  qa[m] = *(const float4*)&Qs[ty*4+m][d4*4];
            #pragma unroll
            for (int n2 = 0; n2 < 4; n2++) kb[n2] = *(const float4*)&Ks[tx*4+n2][d4*4];
            #pragma unroll
            for (int m = 0; m < 4; m++)
                #pragma unroll
                for (int n2 = 0; n2 < 4; n2++)
                    acc[m][n2] += qa[m].x*kb[n2].x + qa[m].y*kb[n2].y
                                + qa[m].z*kb[n2].z + qa[m].w*kb[n2].w;
        }
        __syncthreads();
    }
    #pragma unroll
    for (int m = 0; m < 4; m++) {
        int i = i0 + ty*4 + m;
        #pragma unroll
        for (int n2 = 0; n2 < 4; n2++)
            g_dots[((size_t)(rs*Hh + h)*Nn + i)*Nn + j0 + tx*4 + n2] = acc[m][n2]*0.125f;
    }
}

// ---------------- attention softmax over j (sums the two r-split planes) -------
__global__ void __launch_bounds__(256)
softmax_kernel()
{
    const int row = blockIdx.x;            // h*256 + i
    const int h = row >> 8, i = row & 255, j = threadIdx.x;
    float v = g_dots[(size_t)row*Nn + j]
            + g_dots[(size_t)Hh*Nn*Nn + (size_t)row*Nn + j]
            + g_bias[((size_t)i*Nn + j)*Hh + h];
    __shared__ float red[8];
    const int lane = j & 31, wid = j >> 5;
    float m = v;
    #pragma unroll
    for (int o = 16; o; o >>= 1) m = fmaxf(m, __shfl_xor_sync(0xffffffffu, m, o));
    if (lane == 0) red[wid] = m;
    __syncthreads();
    float bm = red[0];
    #pragma unroll
    for (int k = 1; k < 8; k++) bm = fmaxf(bm, red[k]);
    __syncthreads();
    float e = __expf(v - bm);
    float s = e;
    #pragma unroll
    for (int o = 16; o; o >>= 1) s += __shfl_xor_sync(0xffffffffu, s, o);
    if (lane == 0) red[wid] = s;
    __syncthreads();
    float su = red[0];
    #pragma unroll
    for (int k = 1; k < 8; k++) su += red[k];
    g_attn[(size_t)row*Nn + j] = e/su;
}

// ---------------- out[r,i,h*64+d] = sum_j attn[h,i,j] * v[r,j,h,d] -------------
__global__ void __launch_bounds__(256)
out_kernel()
{
    __shared__ float As[64][68];   // transposed attn [j][i]
    __shared__ float Bs[64][68];   // v [j][d]
    const int t = threadIdx.x, tx = t & 15, ty = t >> 4;
    const int i0 = blockIdx.x*64, h = blockIdx.y, rr = blockIdx.z;
    const int vc = 1024 + h*64;
    float acc[4][4] = {};

    for (int jt = 0; jt < 4; jt++) {
        int j0 = jt*64;
        #pragma unroll
        for (int u = 0; u < 4; u++) {
            int idx = u*256 + t, row = idx >> 4, c4 = idx & 15;
            float4 a = *(const float4*)(g_attn + ((size_t)(h*Nn + i0+row))*Nn + j0 + c4*4);
            As[c4*4+0][row] = a.x;
            As[c4*4+1][row] = a.y;
            As[c4*4+2][row] = a.z;
            As[c4*4+3][row] = a.w;
            *(float4*)&Bs[row][c4*4] =
                *(const float4*)(g_proj + ((size_t)(rr*Nn + j0+row))*PW + vc + c4*4);
        }
        __syncthreads();
        #pragma unroll 16
        for (int jj = 0; jj < 64; jj++) {
            float4 ra = *(const float4*)&As[jj][ty*4];
            float4 rb = *(const float4*)&Bs[jj][tx*4];
            acc[0][0] += ra.x*rb.x; acc[0][1] += ra.x*rb.y; acc[0][2] += ra.x*rb.z; acc[0][3] += ra.x*rb.w;
            acc[1][0] += ra.y*rb.x; acc[1][1] += ra.y*rb.y; acc[1][2] += ra.y*rb.z; acc[1][3] += ra.y*rb.w;
            acc[2][0] += ra.z*rb.x; acc[2][1] += ra.z*rb.y; acc[2][2] += ra.z*rb.z; acc[2][3] += ra.z*rb.w;
            acc[3][0] += ra.w*rb.x; acc[3][1] += ra.w*rb.y; acc[3][2] += ra.w*rb.z; acc[3][3] += ra.w*rb.w;
        }
        __syncthreads();
    }
    #pragma unroll
    for (int m = 0; m < 4; m++) {
        float4 o = make_float4(acc[m][0], acc[m][1], acc[m][2], acc[m][3]);
        *(float4*)&g_ypre[((size_t)(rr*Nn) + i0 + ty*4 + m)*INNERi + h*64 + tx*4] = o;
    }
}

// =================================================================================
extern "C" void kernel_launch(void* const* d_in, const int* in_sizes, int n_in,
                              void* d_out, int out_size)
{
    const float* x    = (const float*)d_in[0];
    const float* pair = (const float*)d_in[1];
    const float* wq   = (const float*)d_in[2];
    const float* wkv  = (const float*)d_in[3];
    const float* wo   = (const float*)d_in[4];
    const float* bo   = (const float*)d_in[5];
    const float* png  = (const float*)d_in[6];
    const float* pnb  = (const float*)d_in[7];
    const float* wp   = (const float*)d_in[8];
    const float* swqw = (const float*)d_in[9];
    const float* swqb = (const float*)d_in[10];
    const float* swkw = (const float*)d_in[11];
    const float* swkb = (const float*)d_in[12];
    float* out = (float*)d_out;

    float *proj, *Wp, *bp, *qswp;
    cudaGetSymbolAddress((void**)&proj, g_proj);
    cudaGetSymbolAddress((void**)&Wp,   g_Wpack);
    cudaGetSymbolAddress((void**)&bp,   g_bpack);
    cudaGetSymbolAddress((void**)&qswp, g_qsw);
    float* ypre;
    cudaGetSymbolAddress((void**)&ypre, g_ypre);

    // 1. pack weights [wq | wkv | swk_w]
    packw_kernel<<<(Dd*PW + 255)/256, 256>>>(wq, wkv, swkw, swkb);
    // 2. fused projection: proj = x @ Wpack + bpack  (q|k|v|ksw)
    sgemm_kernel<<<dim3(PW/64, MROWS/64), 256>>>(x, Wp, bp, proj, MROWS, PW, Dd);
    // 3. qsw = x[0] @ swq_w + swq_b  (first MSA row only)
    sgemm_kernel<<<dim3(Dd/64, Nn/64), 256>>>(x, swqw, swqb, qswp, Nn, Dd, Dd);
    // 4. soft-tied row weights w[n,h,r]
    seqw_kernel<<<Nn*Hh, 128>>>();
    // 5. pair bias LN + Linear -> [i,j,h]
    pairbias_kernel<<<Nn*Nn/8, 256>>>(pair, png, pnb, wp);
    // 6. tied dots (two r-split partial planes)
    dots_kernel<<<dim3(4, 4, 16), 256>>>();
    // 7. attention softmax (dots0 + dots1 + bias)
    softmax_kernel<<<Hh*Nn, 256>>>();
    // 8. out = attn @ V, written as (r,i,h*64+d)
    out_kernel<<<dim3(4, Hh, Rr), 256>>>();
    // 9. final projection: out = ypre @ wo + bo
    sgemm_kernel<<<dim3(Dd/64, MROWS/64), 256>>>(ypre, wo, bo, out, MROWS, Dd, INNERi);
}

// round 2
// speedup vs baseline: 3.3696x; 3.3696x over previous
#include <cuda_runtime.h>
#include <cstdint>

// Problem constants (fixed by setup_inputs)
#define Rr      128
#define Nn      256
#define Dd      128
#define Hh      8
#define DHh     64
#define INNERi  512
#define MROWS   (Rr*Nn)      // 32768
#define PW      1664         // packed proj width: 512 q | 512 k | 512 v | 128 ksw
#define RSPLIT  8            // dots r-split planes

// ---------------- scratch (static device globals; no allocation) ----------------
__device__ float g_proj [(size_t)MROWS*PW];     // 218 MB: q|k|v|ksw rows
__device__ float g_Wpack[Dd*PW];
__device__ float g_bpack[PW];
__device__ float g_qsw  [Nn*Dd];
__device__ float g_w    [Nn*Hh*Rr];             // softmaxed row weights [n][h][r]
__device__ float g_dots [(size_t)RSPLIT*Hh*Nn*Nn];  // r-split partial planes
__device__ float g_bias [Nn*Nn*Hh];             // pair bias -> heads [i][j][h]
__device__ float g_attn [Hh*Nn*Nn];
__device__ float g_ypre [(size_t)MROWS*INNERi]; // 64 MB

// ---------------- tf32 helpers --------------------------------------------------
__device__ __forceinline__ uint32_t f2tf(float v) {
    uint32_t r;
    asm("cvt.rna.tf32.f32 %0, %1;" : "=r"(r) : "f"(v));
    return r;
}

__device__ __forceinline__ void mma_tf32(float* d, const uint32_t* a, const uint32_t* b) {
    asm volatile(
        "mma.sync.aligned.m16n8k8.row.col.f32.tf32.tf32.f32 "
        "{%0,%1,%2,%3}, {%4,%5,%6,%7}, {%8,%9}, {%0,%1,%2,%3};"
        : "+f"(d[0]), "+f"(d[1]), "+f"(d[2]), "+f"(d[3])
        : "r"(a[0]), "r"(a[1]), "r"(a[2]), "r"(a[3]), "r"(b[0]), "r"(b[1]));
}

#define LDA_S 36    // [m][k] pad (bank-conflict-free fragment gather)
#define LDB_S 136   // [k][n] pad

// ---------------- weight packing: [wq | wkv | swk_w], bias = [0 | 0 | swk_b] ----
__global__ void packw_kernel(const float* __restrict__ wq,
                             const float* __restrict__ wkv,
                             const float* __restrict__ swkw,
                             const float* __restrict__ swkb)
{
    int idx = blockIdx.x*blockDim.x + threadIdx.x;
    if (idx < Dd*PW) {
        int k = idx / PW, c = idx % PW;
        float v;
        if      (c < 512)  v = wq  [k*512  + c];
        else if (c < 1536) v = wkv [k*1024 + (c-512)];
        else               v = swkw[k*Dd   + (c-1536)];
        g_Wpack[idx] = v;
    }
    if (idx < PW) g_bpack[idx] = (idx < 1536) ? 0.f : swkb[idx-1536];
}

// ---------------- generic tf32 GEMM: C[M,N] = A[M,K] @ B[K,N] + bias ------------
// block tile 128x128, 8 warps (2x4), warp tile 64x32, k-tile 32
__global__ void __launch_bounds__(256)
tgemm_kernel(const float* __restrict__ A, int lda,
             const float* __restrict__ B, int ldb,
             const float* __restrict__ bias,
             float* __restrict__ C, int ldc, int K)
{
    __shared__ uint32_t As[128*LDA_S];   // [m][k] tf32 bits
    __shared__ uint32_t Bs[32*LDB_S];    // [k][n] tf32 bits
    const int t = threadIdx.x;
    const int m0 = blockIdx.y*128, n0 = blockIdx.x*128;
    const int wid = t >> 5, lane = t & 31;
    const int wm = (wid & 1)*64, wn = (wid >> 1)*32;
    const int g = lane >> 2, tig = lane & 3;
    float acc[4][4][4] = {};

    for (int k0 = 0; k0 < K; k0 += 32) {
        #pragma unroll
        for (int u = 0; u < 4; u++) {            // A: 128x32
            int idx = u*256 + t, row = idx >> 3, c4 = (idx & 7)*4;
            float4 a = *(const float4*)&A[(size_t)(m0+row)*lda + k0 + c4];
            uint32_t* p = &As[row*LDA_S + c4];
            p[0] = f2tf(a.x); p[1] = f2tf(a.y); p[2] = f2tf(a.z); p[3] = f2tf(a.w);
        }
        #pragma unroll
        for (int u = 0; u < 4; u++) {            // B: 32x128
            int idx = u*256 + t, row = idx >> 5, c4 = (idx & 31)*4;
            float4 b = *(const float4*)&B[(size_t)(k0+row)*ldb + n0 + c4];
            uint32_t* p = &Bs[row*LDB_S + c4];
            p[0] = f2tf(b.x); p[1] = f2tf(b.y); p[2] = f2tf(b.z); p[3] = f2tf(b.w);
        }
        __syncthreads();
        #pragma unroll
        for (int ks = 0; ks < 4; ks++) {
            uint32_t af[4][4], bf[4][2];
            #pragma unroll
            for (int mf = 0; mf < 4; mf++) {
                const uint32_t* ap = &As[(wm + mf*16 + g)*LDA_S + ks*8 + tig];
                af[mf][0] = ap[0];         af[mf][1] = ap[8*LDA_S];
                af[mf][2] = ap[4];         af[mf][3] = ap[8*LDA_S + 4];
            }
            #pragma unroll
            for (int nf = 0; nf < 4; nf++) {
                const uint32_t* bp = &Bs[(ks*8 + tig)*LDB_S + wn + nf*8 + g];
                bf[nf][0] = bp[0];         bf[nf][1] = bp[4*LDB_S];
            }
            #pragma unroll
            for (int mf = 0; mf < 4; mf++)
                #pragma unroll
                for (int nf = 0; nf < 4; nf++)
                    mma_tf32(acc[mf][nf], af[mf], bf[nf]);
        }
        __syncthreads();
    }
    #pragma unroll
    for (int mf = 0; mf < 4; mf++) {
        int r0 = m0 + wm + mf*16 + g;
        #pragma unroll
        for (int nf = 0; nf < 4; nf++) {
            int c = n0 + wn + nf*8 + 2*tig;
            float b0 = 0.f, b1 = 0.f;
            if (bias) { b0 = bias[c]; b1 = bias[c+1]; }
            *(float2*)&C[(size_t)r0*ldc + c] =
                make_float2(acc[mf][nf][0] + b0, acc[mf][nf][1] + b1);
            *(float2*)&C[(size_t)(r0+8)*ldc + c] =
                make_float2(acc[mf][nf][2] + b0, acc[mf][nf][3] + b1);
        }
    }
}

// ---------------- small fp32 sgemm (kept for qsw: 256x128x128) ------------------
__global__ void __launch_bounds__(256)
sgemm_kernel(const float* __restrict__ A, const float* __restrict__ B,
             const float* __restrict__ bias, float* __restrict__ C,
             int M, int N, int K)
{
    __shared__ float As[16][68];
    __shared__ float Bs[16][64];
    const int t  = threadIdx.x;
    const int tx = t & 15, ty = t >> 4;
    const int n0 = blockIdx.x*64, m0 = blockIdx.y*64;
    const int arow = t >> 2, ak4 = t & 3;
    const int brow = t >> 4, bc4 = t & 15;
    float acc[4][4] = {};

    for (int k0 = 0; k0 < K; k0 += 16) {
        float4 a = *(const float4*)&A[(size_t)(m0+arow)*K + k0 + ak4*4];
        As[ak4*4+0][arow] = a.x;
        As[ak4*4+1][arow] = a.y;
        As[ak4*4+2][arow] = a.z;
        As[ak4*4+3][arow] = a.w;
        *(float4*)&Bs[brow][bc4*4] =
            *(const float4*)&B[(size_t)(k0+brow)*N + n0 + bc4*4];
        __syncthreads();
        #pragma unroll
        for (int kk = 0; kk < 16; kk++) {
            float4 ra = *(const float4*)&As[kk][ty*4];
            float4 rb = *(const float4*)&Bs[kk][tx*4];
            acc[0][0] += ra.x*rb.x; acc[0][1] += ra.x*rb.y; acc[0][2] += ra.x*rb.z; acc[0][3] += ra.x*rb.w;
            acc[1][0] += ra.y*rb.x; acc[1][1] += ra.y*rb.y; acc[1][2] += ra.y*rb.z; acc[1][3] += ra.y*rb.w;
            acc[2][0] += ra.z*rb.x; acc[2][1] += ra.z*rb.y; acc[2][2] += ra.z*rb.z; acc[2][3] += ra.z*rb.w;
            acc[3][0] += ra.w*rb.x; acc[3][1] += ra.w*rb.y; acc[3][2] += ra.w*rb.z; acc[3][3] += ra.w*rb.w;
        }
        __syncthreads();
    }
    float4 bv = make_float4(0.f,0.f,0.f,0.f);
    if (bias) bv = *(const float4*)&bias[n0 + tx*4];
    #pragma unroll
    for (int m = 0; m < 4; m++) {
        float4 o = make_float4(acc[m][0]+bv.x, acc[m][1]+bv.y,
                               acc[m][2]+bv.z, acc[m][3]+bv.w);
        *(float4*)&C[(size_t)(m0 + ty*4 + m)*N + n0 + tx*4] = o;
    }
}

// ---------------- positional seq-weight: logits + softmax over r ----------------
__global__ void __launch_bounds__(128)
seqw_kernel()
{
    const int n = blockIdx.x >> 3, h = blockIdx.x & 7;
    const int r = threadIdx.x;
    __shared__ float qs[16];
    __shared__ float red[4];
    if (r < 16) qs[r] = g_qsw[n*Dd + h*16 + r];
    __syncthreads();
    const float* kp = g_proj + ((size_t)(r*Nn + n))*PW + 1536 + h*16;
    float s = 0.f;
    #pragma unroll
    for (int d = 0; d < 16; d++) s += qs[d]*kp[d];
    s *= 0.25f;
    const int lane = r & 31, wid = r >> 5;
    float m = s;
    #pragma unroll
    for (int o = 16; o; o >>= 1) m = fmaxf(m, __shfl_xor_sync(0xffffffffu, m, o));
    if (lane == 0) red[wid] = m;
    __syncthreads();
    m = fmaxf(fmaxf(red[0],red[1]), fmaxf(red[2],red[3]));
    __syncthreads();
    float e = __expf(s - m);
    float su = e;
    #pragma unroll
    for (int o = 16; o; o >>= 1) su += __shfl_xor_sync(0xffffffffu, su, o);
    if (lane == 0) red[wid] = su;
    __syncthreads();
    su = red[0]+red[1]+red[2]+red[3];
    g_w[(n*Hh + h)*Rr + r] = e/su;
}

// ---------------- pair bias: per-(i,j) LayerNorm + Linear(128->8) --------------
__global__ void __launch_bounds__(256)
pairbias_kernel(const float* __restrict__ pb, const float* __restrict__ gg,
                const float* __restrict__ bb, const float* __restrict__ wp)
{
    __shared__ float s_wp[Dd*Hh];
    __shared__ float s_g[Dd], s_b[Dd];
    const int t = threadIdx.x;
    for (int k = t; k < Dd*Hh; k += 256) s_wp[k] = wp[k];
    if (t < Dd) { s_g[t] = gg[t]; s_b[t] = bb[t]; }
    __syncthreads();
    const int warp = t >> 5, lane = t & 31;
    const int p = blockIdx.x*8 + warp;
    const float* rowp = pb + (size_t)p*Dd;
    float v[4];
    #pragma unroll
    for (int u = 0; u < 4; u++) v[u] = rowp[lane + 32*u];
    float s = v[0]+v[1]+v[2]+v[3];
    #pragma unroll
    for (int o = 16; o; o >>= 1) s += __shfl_xor_sync(0xffffffffu, s, o);
    const float mu = s * (1.f/128.f);
    float q = 0.f;
    #pragma unroll
    for (int u = 0; u < 4; u++) { float d = v[u]-mu; q += d*d; }
    #pragma unroll
    for (int o = 16; o; o >>= 1) q += __shfl_xor_sync(0xffffffffu, q, o);
    const float rstd = rsqrtf(q*(1.f/128.f) + 1e-5f);
    float acc[8] = {};
    #pragma unroll
    for (int u = 0; u < 4; u++) {
        int c = lane + 32*u;
        float ln = (v[u]-mu)*rstd*s_g[c] + s_b[c];
        #pragma unroll
        for (int h = 0; h < 8; h++) acc[h] += ln*s_wp[c*8 + h];
    }
    #pragma unroll
    for (int h = 0; h < 8; h++)
        #pragma unroll
        for (int o = 16; o; o >>= 1) acc[h] += __shfl_xor_sync(0xffffffffu, acc[h], o);
    float outv = 0.f;
    #pragma unroll
    for (int h = 0; h < 8; h++) if (lane == h) outv = acc[h];
    if (lane < 8) g_bias[(size_t)p*8 + lane] = outv;
}

// ---------------- tied dots (tf32 MMA) ------------------------------------------
// dots[h,i,j] partial over r-chunk rc: sum_{r in chunk, d} w[i,h,r]q[r,i,h,d]k[r,j,h,d]
// block: 128(i) x 128(j); both tiles stored [row][k] (pad 36) — no transpose needed
__global__ void __launch_bounds__(256)
dots_tf32_kernel()
{
    __shared__ uint32_t Qs[128*LDA_S];   // [i][d]
    __shared__ uint32_t Ks[128*LDA_S];   // [j][d]
    const int t = threadIdx.x;
    const int j0 = blockIdx.x*128, i0 = blockIdx.y*128;
    const int h = blockIdx.z & 7, rc = blockIdx.z >> 3;
    const int wid = t >> 5, lane = t & 31;
    const int wm = (wid & 1)*64, wn = (wid >> 1)*32;
    const int g = lane >> 2, tig = lane & 3;
    float acc[4][4][4] = {};

    for (int r = rc*(Rr/RSPLIT); r < (rc+1)*(Rr/RSPLIT); ++r) {
        #pragma unroll
        for (int dt = 0; dt < 2; dt++) {
            const int d0 = dt*32;
            #pragma unroll
            for (int u = 0; u < 4; u++) {
                int idx = u*256 + t, row = idx >> 3, c4 = (idx & 7)*4;
                float4 a = *(const float4*)(g_proj + ((size_t)(r*Nn + i0+row))*PW + h*64 + d0 + c4);
                float sc = g_w[((i0+row)*Hh + h)*Rr + r];
                uint32_t* p = &Qs[row*LDA_S + c4];
                p[0] = f2tf(a.x*sc); p[1] = f2tf(a.y*sc); p[2] = f2tf(a.z*sc); p[3] = f2tf(a.w*sc);
                float4 b = *(const float4*)(g_proj + ((size_t)(r*Nn + j0+row))*PW + 512 + h*64 + d0 + c4);
                uint32_t* q = &Ks[row*LDA_S + c4];
                q[0] = f2tf(b.x); q[1] = f2tf(b.y); q[2] = f2tf(b.z); q[3] = f2tf(b.w);
            }
            __syncthreads();
            #pragma unroll
            for (int ks = 0; ks < 4; ks++) {
                uint32_t af[4][4], bf[4][2];
                #pragma unroll
                for (int mf = 0; mf < 4; mf++) {
                    const uint32_t* ap = &Qs[(wm + mf*16 + g)*LDA_S + ks*8 + tig];
                    af[mf][0] = ap[0];       af[mf][1] = ap[8*LDA_S];
                    af[mf][2] = ap[4];       af[mf][3] = ap[8*LDA_S + 4];
                }
                #pragma unroll
                for (int nf = 0; nf < 4; nf++) {
                    const uint32_t* bp = &Ks[(wn + nf*8 + g)*LDA_S + ks*8 + tig];
                    bf[nf][0] = bp[0];       bf[nf][1] = bp[4];
                }
                #pragma unroll
                for (int mf = 0; mf < 4; mf++)
                    #pragma unroll
                    for (int nf = 0; nf < 4; nf++)
                        mma_tf32(acc[mf][nf], af[mf], bf[nf]);
            }
            __syncthreads();
        }
    }
    float* plane = g_dots + ((size_t)(rc*Hh + h))*Nn*Nn;
    #pragma unroll
    for (int mf = 0; mf < 4; mf++) {
        int i = i0 + wm + mf*16 + g;
        #pragma unroll
        for (int nf = 0; nf < 4; nf++) {
            int j = j0 + wn + nf*8 + 2*tig;
            *(float2*)&plane[(size_t)i*Nn + j] =
                make_float2(acc[mf][nf][0]*0.125f, acc[mf][nf][1]*0.125f);
            *(float2*)&plane[(size_t)(i+8)*Nn + j] =
                make_float2(acc[mf][nf][2]*0.125f, acc[mf][nf][3]*0.125f);
        }
    }
}

// ---------------- attention softmax over j (sums RSPLIT partial planes) ---------
__global__ void __launch_bounds__(256)
softmax_kernel()
{
    const int row = blockIdx.x;            // h*256 + i
    const int h = row >> 8, i = row & 255, j = threadIdx.x;
    float v = g_bias[((size_t)i*Nn + j)*Hh + h];
    #pragma unroll
    for (int p = 0; p < RSPLIT; p++)
        v += g_dots[(((size_t)(p*Hh + h))*Nn + i)*Nn + j];
    __shared__ float red[8];
    const int lane = j & 31, wid = j >> 5;
    float m = v;
    #pragma unroll
    for (int o = 16; o; o >>= 1) m = fmaxf(m, __shfl_xor_sync(0xffffffffu, m, o));
    if (lane == 0) red[wid] = m;
    __syncthreads();
    float bm = red[0];
    #pragma unroll
    for (int k = 1; k < 8; k++) bm = fmaxf(bm, red[k]);
    __syncthreads();
    float e = __expf(v - bm);
    float s = e;
    #pragma unroll
    for (int o = 16; o; o >>= 1) s += __shfl_xor_sync(0xffffffffu, s, o);
    if (lane == 0) red[wid] = s;
    __syncthreads();
    float su = red[0];
    #pragma unroll
    for (int k = 1; k < 8; k++) su += red[k];
    g_attn[(size_t)row*Nn + j] = e/su;
}

// ---------------- attn@V (tf32 MMA): ypre[r,i,h*64+d] = sum_j attn[h,i,j]v[r,j,h,d]
// block: 128(i) x 64(d) per (r,h); warps 4x2, warp tile 32x32
__global__ void __launch_bounds__(256)
attnv_tf32_kernel()
{
    __shared__ uint32_t As[128*LDA_S];   // attn [i][j-k]
    __shared__ uint32_t Bs[32*72];       // v [j-k][d]
    const int t = threadIdx.x;
    const int i0 = blockIdx.x*128, h = blockIdx.y, r = blockIdx.z;
    const int wid = t >> 5, lane = t & 31;
    const int wm = (wid & 3)*32, wn = (wid >> 2)*32;
    const int g = lane >> 2, tig = lane & 3;
    float acc[2][4][4] = {};

    for (int k0 = 0; k0 < Nn; k0 += 32) {
        #pragma unroll
        for (int u = 0; u < 4; u++) {            // A: 128x32 from attn
            int idx = u*256 + t, row = idx >> 3, c4 = (idx & 7)*4;
            float4 a = *(const float4*)(g_attn + ((size_t)(h*Nn + i0+row))*Nn + k0 + c4);
            uint32_t* p = &As[row*LDA_S + c4];
            p[0] = f2tf(a.x); p[1] = f2tf(a.y); p[2] = f2tf(a.z); p[3] = f2tf(a.w);
        }
        #pragma unroll
        for (int u = 0; u < 2; u++) {            // B: 32x64 from v
            int idx = u*256 + t, row = idx >> 4, c4 = (idx & 15)*4;
            float4 b = *(const float4*)(g_proj + ((size_t)(r*Nn + k0+row))*PW + 1024 + h*64 + c4);
            uint32_t* p = &Bs[row*72 + c4];
            p[0] = f2tf(b.x); p[1] = f2tf(b.y); p[2] = f2tf(b.z); p[3] = f2tf(b.w);
        }
        __syncthreads();
        #pragma unroll
        for (int ks = 0; ks < 4; ks++) {
            uint32_t af[2][4], bf[4][2];
            #pragma unroll
            for (int mf = 0; mf < 2; mf++) {
                const uint32_t* ap = &As[(wm + mf*16 + g)*LDA_S + ks*8 + tig];
                af[mf][0] = ap[0];       af[mf][1] = ap[8*LDA_S];
                af[mf][2] = ap[4];       af[mf][3] = ap[8*LDA_S + 4];
            }
            #pragma unroll
            for (int nf = 0; nf < 4; nf++) {
                const uint32_t* bp = &Bs[(ks*8 + tig)*72 + wn + nf*8 + g];
                bf[nf][0] = bp[0];       bf[nf][1] = bp[4*72];
            }
            #pragma unroll
            for (int mf = 0; mf < 2; mf++)
                #pragma unroll
                for (int nf = 0; nf < 4; nf++)
                    mma_tf32(acc[mf][nf], af[mf], bf[nf]);
        }
        __syncthreads();
    }
    #pragma unroll
    for (int mf = 0; mf < 2; mf++) {
        int i = i0 + wm + mf*16 + g;
        #pragma unroll
        for (int nf = 0; nf < 4; nf++) {
            int c = h*64 + wn + nf*8 + 2*tig;
            *(float2*)&g_ypre[((size_t)(r*Nn) + i)*INNERi + c] =
                make_float2(acc[mf][nf][0], acc[mf][nf][1]);
            *(float2*)&g_ypre[((size_t)(r*Nn) + i + 8)*INNERi + c] =
                make_float2(acc[mf][nf][2], acc[mf][nf][3]);
        }
    }
}

// =================================================================================
extern "C" void kernel_launch(void* const* d_in, const int* in_sizes, int n_in,
                              void* d_out, int out_size)
{
    const float* x    = (const float*)d_in[0];
    const float* pair = (const float*)d_in[1];
    const float* wq   = (const float*)d_in[2];
    const float* wkv  = (const float*)d_in[3];
    const float* wo   = (const float*)d_in[4];
    const float* bo   = (const float*)d_in[5];
    const float* png  = (const float*)d_in[6];
    const float* pnb  = (const float*)d_in[7];
    const float* wp   = (const float*)d_in[8];
    const float* swqw = (const float*)d_in[9];
    const float* swqb = (const float*)d_in[10];
    const float* swkw = (const float*)d_in[11];
    const float* swkb = (const float*)d_in[12];
    float* out = (float*)d_out;

    float *proj, *Wp, *bp, *qswp, *ypre;
    cudaGetSymbolAddress((void**)&proj, g_proj);
    cudaGetSymbolAddress((void**)&Wp,   g_Wpack);
    cudaGetSymbolAddress((void**)&bp,   g_bpack);
    cudaGetSymbolAddress((void**)&qswp, g_qsw);
    cudaGetSymbolAddress((void**)&ypre, g_ypre);

    // 1. pack weights [wq | wkv | swk_w]
    packw_kernel<<<(Dd*PW + 255)/256, 256>>>(wq, wkv, swkw, swkb);
    // 2. fused projection (tf32): proj = x @ Wpack + bpack  (q|k|v|ksw)
    tgemm_kernel<<<dim3(PW/128, MROWS/128), 256>>>(x, Dd, Wp, PW, bp, proj, PW, Dd);
    // 3. qsw = x[0] @ swq_w + swq_b  (first MSA row only; tiny, fp32)
    sgemm_kernel<<<dim3(Dd/64, Nn/64), 256>>>(x, swqw, swqb, qswp, Nn, Dd, Dd);
    // 4. soft-tied row weights w[n,h,r]
    seqw_kernel<<<Nn*Hh, 128>>>();
    // 5. pair bias LN + Linear -> [i,j,h]
    pairbias_kernel<<<Nn*Nn/8, 256>>>(pair, png, pnb, wp);
    // 6. tied dots (tf32, RSPLIT partial planes)
    dots_tf32_kernel<<<dim3(Nn/128, Nn/128, RSPLIT*Hh), 256>>>();
    // 7. attention softmax (sum planes + bias)
    softmax_kernel<<<Hh*Nn, 256>>>();
    // 8. ypre = attn @ V  (tf32), written as (r,i,h*64+d)
    attnv_tf32_kernel<<<dim3(Nn/128, Hh, Rr), 256>>>();
    // 9. final projection (tf32): out = ypre @ wo + bo
    tgemm_kernel<<<dim3(Dd/128, MROWS/128), 256>>>(ypre, INNERi, wo, Dd, bo, out, Dd, INNERi);
}

// round 4
// speedup vs baseline: 4.8742x; 1.4465x over previous
#include <cuda_runtime.h>
#include <cuda_fp16.h>
#include <cstdint>

// Problem constants (fixed by setup_inputs)
#define Rr      128
#define Nn      256
#define Dd      128
#define Hh      8
#define DHh     64
#define INNERi  512
#define MROWS   (Rr*Nn)      // 32768
#define PW      1664         // packed proj cols: 512 q | 512 k | 512 v | 128 ksw
#define RSPLIT  8            // dots r-split planes
#define LDH     72           // smem half-row pitch (bank-conflict-free fragments)

// ---------------- scratch (static device globals; no allocation) ----------------
__device__ __half g_proj [(size_t)MROWS*PW];     // 109 MB: q|k|v|ksw (half)
__device__ __half g_xh   [(size_t)MROWS*Dd];     // x in half
__device__ __half g_WpT  [(size_t)PW*Dd];        // packed proj weights, [n][k] half
__device__ float  g_bpack[PW];
__device__ __half g_woT  [Dd*INNERi];            // wo^T [n][k] half
__device__ float  g_qsw  [Nn*Dd];
__device__ float  g_w    [Nn*Hh*Rr];             // softmaxed row weights [n][h][r]
__device__ float  g_dots [(size_t)RSPLIT*Hh*Nn*Nn];
__device__ float  g_bias [Nn*Nn*Hh];             // pair bias -> heads [i][j][h]
__device__ __half g_attn [Hh*Nn*Nn];
__device__ __half g_ypre [(size_t)MROWS*INNERi]; // 32 MB

// ---------------- fp16 mma helper ------------------------------------------------
__device__ __forceinline__ void mma_f16(float* d, const uint32_t* a, const uint32_t* b) {
    asm volatile(
        "mma.sync.aligned.m16n8k16.row.col.f32.f16.f16.f32 "
        "{%0,%1,%2,%3}, {%4,%5,%6,%7}, {%8,%9}, {%0,%1,%2,%3};"
        : "+f"(d[0]), "+f"(d[1]), "+f"(d[2]), "+f"(d[3])
        : "r"(a[0]), "r"(a[1]), "r"(a[2]), "r"(a[3]), "r"(b[0]), "r"(b[1]));
}

__device__ __forceinline__ uint32_t pack_h2(__half lo, __half hi) {
    __half2 h = __halves2half2(lo, hi);
    return *(uint32_t*)&h;
}

// ---------------- prep: convert x to half ----------------------------------------
__global__ void cvtx_kernel(const float* __restrict__ x)
{
    int i4 = (blockIdx.x*blockDim.x + threadIdx.x) * 4;
    if (i4 < MROWS*Dd) {
        float4 v = *(const float4*)&x[i4];
        __half2* p = (__half2*)&g_xh[i4];
        p[0] = __floats2half2_rn(v.x, v.y);
        p[1] = __floats2half2_rn(v.z, v.w);
    }
}

// ---------------- prep: pack weights ---------------------------------------------
// g_WpT[c][k] = [wq | wkv | swk_w]^T (half); g_bpack = [0|0|0|swk_b];
// g_woT[n][k] = wo^T (half)
__global__ void packw_kernel(const float* __restrict__ wq,
                             const float* __restrict__ wkv,
                             const float* __restrict__ swkw,
                             const float* __restrict__ swkb,
                             const float* __restrict__ wo)
{
    int idx = blockIdx.x*blockDim.x + threadIdx.x;
    if (idx < PW*Dd) {
        int c = idx >> 7, k = idx & 127;
        float v;
        if      (c < 512)  v = wq  [k*512  + c];
        else if (c < 1536) v = wkv [k*1024 + (c-512)];
        else               v = swkw[k*Dd   + (c-1536)];
        g_WpT[idx] = __float2half(v);
    }
    if (idx < Dd*INNERi) {
        int n = idx >> 9, k = idx & 511;
        g_woT[idx] = __float2half(wo[k*Dd + n]);
    }
    if (idx < PW) g_bpack[idx] = (idx < 1536) ? 0.f : swkb[idx-1536];
}

// ---------------- generic fp16 GEMM: C[M,N] = A[M,K] @ Bt[N,K]^T + bias ----------
// block 128x128, 8 warps (2x4), warp tile 64x32, k-slab 64
template<bool OUTH>
__global__ void __launch_bounds__(256)
hgemm_kernel(const __half* __restrict__ A, int lda,
             const __half* __restrict__ Bt, int ldb,
             const float* __restrict__ bias,
             void* __restrict__ Cv, int ldc, int K)
{
    __shared__ __half As[128*LDH];
    __shared__ __half Bs[128*LDH];
    const int t = threadIdx.x;
    const int m0 = blockIdx.y*128, n0 = blockIdx.x*128;
    const int wid = t >> 5, lane = t & 31;
    const int wm = (wid & 1)*64, wn = (wid >> 1)*32;
    const int g = lane >> 2, tig = lane & 3;
    float acc[4][4][4] = {};

    for (int k0 = 0; k0 < K; k0 += 64) {
        #pragma unroll
        for (int u = 0; u < 4; u++) {
            int idx = u*256 + t, row = idx >> 3, c8 = (idx & 7)*8;
            *(float4*)&As[row*LDH + c8] =
                *(const float4*)&A[(size_t)(m0+row)*lda + k0 + c8];
            *(float4*)&Bs[row*LDH + c8] =
                *(const float4*)&Bt[(size_t)(n0+row)*ldb + k0 + c8];
        }
        __syncthreads();
        #pragma unroll
        for (int ks = 0; ks < 4; ks++) {
            uint32_t af[4][4], bf[4][2];
            #pragma unroll
            for (int mf = 0; mf < 4; mf++) {
                const __half* ap = &As[(wm + mf*16 + g)*LDH + ks*16 + 2*tig];
                af[mf][0] = *(const uint32_t*)ap;
                af[mf][1] = *(const uint32_t*)(ap + 8*LDH);
                af[mf][2] = *(const uint32_t*)(ap + 8);
                af[mf][3] = *(const uint32_t*)(ap + 8*LDH + 8);
            }
            #pragma unroll
            for (int nf = 0; nf < 4; nf++) {
                const __half* bp = &Bs[(wn + nf*8 + g)*LDH + ks*16 + 2*tig];
                bf[nf][0] = *(const uint32_t*)bp;
                bf[nf][1] = *(const uint32_t*)(bp + 8);
            }
            #pragma unroll
            for (int mf = 0; mf < 4; mf++)
                #pragma unroll
                for (int nf = 0; nf < 4; nf++)
                    mma_f16(acc[mf][nf], af[mf], bf[nf]);
        }
        __syncthreads();
    }
    #pragma unroll
    for (int mf = 0; mf < 4; mf++) {
        int r0 = m0 + wm + mf*16 + g;
        #pragma unroll
        for (int nf = 0; nf < 4; nf++) {
            int c = n0 + wn + nf*8 + 2*tig;
            float b0 = 0.f, b1 = 0.f;
            if (bias) { b0 = bias[c]; b1 = bias[c+1]; }
            if (OUTH) {
                __half* C = (__half*)Cv;
                *(__half2*)&C[(size_t)r0*ldc + c] =
                    __floats2half2_rn(acc[mf][nf][0]+b0, acc[mf][nf][1]+b1);
                *(__half2*)&C[(size_t)(r0+8)*ldc + c] =
                    __floats2half2_rn(acc[mf][nf][2]+b0, acc[mf][nf][3]+b1);
            } else {
                float* C = (float*)Cv;
                *(float2*)&C[(size_t)r0*ldc + c] =
                    make_float2(acc[mf][nf][0]+b0, acc[mf][nf][1]+b1);
                *(float2*)&C[(size_t)(r0+8)*ldc + c] =
                    make_float2(acc[mf][nf][2]+b0, acc[mf][nf][3]+b1);
            }
        }
    }
}

// ---------------- small fp32 sgemm (qsw: 256x128x128) ----------------------------
__global__ void __launch_bounds__(256)
sgemm_kernel(const float* __restrict__ A, const float* __restrict__ B,
             const float* __restrict__ bias, float* __restrict__ C,
             int M, int N, int K)
{
    __shared__ float As[16][68];
    __shared__ float Bs[16][64];
    const int t  = threadIdx.x;
    const int tx = t & 15, ty = t >> 4;
    const int n0 = blockIdx.x*64, m0 = blockIdx.y*64;
    const int arow = t >> 2, ak4 = t & 3;
    const int brow = t >> 4, bc4 = t & 15;
    float acc[4][4] = {};

    for (int k0 = 0; k0 < K; k0 += 16) {
        float4 a = *(const float4*)&A[(size_t)(m0+arow)*K + k0 + ak4*4];
        As[ak4*4+0][arow] = a.x;
        As[ak4*4+1][arow] = a.y;
        As[ak4*4+2][arow] = a.z;
        As[ak4*4+3][arow] = a.w;
        *(float4*)&Bs[brow][bc4*4] =
            *(const float4*)&B[(size_t)(k0+brow)*N + n0 + bc4*4];
        __syncthreads();
        #pragma unroll
        for (int kk = 0; kk < 16; kk++) {
            float4 ra = *(const float4*)&As[kk][ty*4];
            float4 rb = *(const float4*)&Bs[kk][tx*4];
            acc[0][0] += ra.x*rb.x; acc[0][1] += ra.x*rb.y; acc[0][2] += ra.x*rb.z; acc[0][3] += ra.x*rb.w;
            acc[1][0] += ra.y*rb.x; acc[1][1] += ra.y*rb.y; acc[1][2] += ra.y*rb.z; acc[1][3] += ra.y*rb.w;
            acc[2][0] += ra.z*rb.x; acc[2][1] += ra.z*rb.y; acc[2][2] += ra.z*rb.z; acc[2][3] += ra.z*rb.w;
            acc[3][0] += ra.w*rb.x; acc[3][1] += ra.w*rb.y; acc[3][2] += ra.w*rb.z; acc[3][3] += ra.w*rb.w;
        }
        __syncthreads();
    }
    float4 bv = make_float4(0.f,0.f,0.f,0.f);
    if (bias) bv = *(const float4*)&bias[n0 + tx*4];
    #pragma unroll
    for (int m = 0; m < 4; m++) {
        float4 o = make_float4(acc[m][0]+bv.x, acc[m][1]+bv.y,
                               acc[m][2]+bv.z, acc[m][3]+bv.w);
        *(float4*)&C[(size_t)(m0 + ty*4 + m)*N + n0 + tx*4] = o;
    }
}

// ---------------- positional seq-weight: logits + softmax over r -----------------
__global__ void __launch_bounds__(128)
seqw_kernel()
{
    const int n = blockIdx.x >> 3, h = blockIdx.x & 7;
    const int r = threadIdx.x;
    __shared__ float qs[16];
    __shared__ float red[4];
    if (r < 16) qs[r] = g_qsw[n*Dd + h*16 + r];
    __syncthreads();
    const __half* kp = g_proj + ((size_t)(r*Nn + n))*PW + 1536 + h*16;
    float s = 0.f;
    #pragma unroll
    for (int d = 0; d < 16; d++) s += qs[d]*__half2float(kp[d]);
    s *= 0.25f;
    const int lane = r & 31, wid = r >> 5;
    float m = s;
    #pragma unroll
    for (int o = 16; o; o >>= 1) m = fmaxf(m, __shfl_xor_sync(0xffffffffu, m, o));
    if (lane == 0) red[wid] = m;
    __syncthreads();
    m = fmaxf(fmaxf(red[0],red[1]), fmaxf(red[2],red[3]));
    __syncthreads();
    float e = __expf(s - m);
    float su = e;
    #pragma unroll
    for (int o = 16; o; o >>= 1) su += __shfl_xor_sync(0xffffffffu, su, o);
    if (lane == 0) red[wid] = su;
    __syncthreads();
    su = red[0]+red[1]+red[2]+red[3];
    g_w[(n*Hh + h)*Rr + r] = e/su;
}

// ---------------- pair bias: per-(i,j) LayerNorm + Linear(128->8) ----------------
__global__ void __launch_bounds__(256)
pairbias_kernel(const float* __restrict__ pb, const float* __restrict__ gg,
                const float* __restrict__ bb, const float* __restrict__ wp)
{
    __shared__ float s_wp[Dd*Hh];
    __shared__ float s_g[Dd], s_b[Dd];
    const int t = threadIdx.x;
    for (int k = t; k < Dd*Hh; k += 256) s_wp[k] = wp[k];
    if (t < Dd) { s_g[t] = gg[t]; s_b[t] = bb[t]; }
    __syncthreads();
    const int warp = t >> 5, lane = t & 31;
    const int p = blockIdx.x*8 + warp;
    const float* rowp = pb + (size_t)p*Dd;
    float v[4];
    #pragma unroll
    for (int u = 0; u < 4; u++) v[u] = rowp[lane + 32*u];
    float s = v[0]+v[1]+v[2]+v[3];
    #pragma unroll
    for (int o = 16; o; o >>= 1) s += __shfl_xor_sync(0xffffffffu, s, o);
    const float mu = s * (1.f/128.f);
    float q = 0.f;
    #pragma unroll
    for (int u = 0; u < 4; u++) { float d = v[u]-mu; q += d*d; }
    #pragma unroll
    for (int o = 16; o; o >>= 1) q += __shfl_xor_sync(0xffffffffu, q, o);
    const float rstd = rsqrtf(q*(1.f/128.f) + 1e-5f);
    float acc[8] = {};
    #pragma unroll
    for (int u = 0; u < 4; u++) {
        int c = lane + 32*u;
        float ln = (v[u]-mu)*rstd*s_g[c] + s_b[c];
        #pragma unroll
        for (int h = 0; h < 8; h++) acc[h] += ln*s_wp[c*8 + h];
    }
    #pragma unroll
    for (int h = 0; h < 8; h++)
        #pragma unroll
        for (int o = 16; o; o >>= 1) acc[h] += __shfl_xor_sync(0xffffffffu, acc[h], o);
    float outv = 0.f;
    #pragma unroll
    for (int h = 0; h < 8; h++) if (lane == h) outv = acc[h];
    if (lane < 8) g_bias[(size_t)p*8 + lane] = outv;
}

// ---------------- tied dots (fp16 MMA) -------------------------------------------
// dots[h,i,j] partial over r-chunk rc: sum_{r,d} w[i,h,r]q[r,i,h,d]k[r,j,h,d]
__global__ void __launch_bounds__(256)
dots_f16_kernel()
{
    __shared__ __half Qs[128*LDH];   // [i][d] (w-scaled)
    __shared__ __half Ks[128*LDH];   // [j][d]
    const int t = threadIdx.x;
    const int j0 = blockIdx.x*128, i0 = blockIdx.y*128;
    const int h = blockIdx.z & 7, rc = blockIdx.z >> 3;
    const int wid = t >> 5, lane = t & 31;
    const int wm = (wid & 1)*64, wn = (wid >> 1)*32;
    const int g = lane >> 2, tig = lane & 3;
    float acc[4][4][4] = {};

    for (int r = rc*(Rr/RSPLIT); r < (rc+1)*(Rr/RSPLIT); ++r) {
        #pragma unroll
        for (int u = 0; u < 4; u++) {
            int idx = u*256 + t, row = idx >> 3, c8 = (idx & 7)*8;
            // Q tile, scaled by w[i,h,r]
            float4 a = *(const float4*)(g_proj + ((size_t)(r*Nn + i0+row))*PW + h*64 + c8);
            float sc = g_w[((i0+row)*Hh + h)*Rr + r];
            __half2 sc2 = __float2half2_rn(sc);
            __half2* ah = (__half2*)&a;
            ah[0] = __hmul2(ah[0], sc2); ah[1] = __hmul2(ah[1], sc2);
            ah[2] = __hmul2(ah[2], sc2); ah[3] = __hmul2(ah[3], sc2);
            *(float4*)&Qs[row*LDH + c8] = a;
            // K tile
            *(float4*)&Ks[row*LDH + c8] =
                *(const float4*)(g_proj + ((size_t)(r*Nn + j0+row))*PW + 512 + h*64 + c8);
        }
        __syncthreads();
        #pragma unroll
        for (int ks = 0; ks < 4; ks++) {
            uint32_t af[4][4], bf[4][2];
            #pragma unroll
            for (int mf = 0; mf < 4; mf++) {
                const __half* ap = &Qs[(wm + mf*16 + g)*LDH + ks*16 + 2*tig];
                af[mf][0] = *(const uint32_t*)ap;
                af[mf][1] = *(const uint32_t*)(ap + 8*LDH);
                af[mf][2] = *(const uint32_t*)(ap + 8);
                af[mf][3] = *(const uint32_t*)(ap + 8*LDH + 8);
            }
            #pragma unroll
            for (int nf = 0; nf < 4; nf++) {
                const __half* bp = &Ks[(wn + nf*8 + g)*LDH + ks*16 + 2*tig];
                bf[nf][0] = *(const uint32_t*)bp;
                bf[nf][1] = *(const uint32_t*)(bp + 8);
            }
            #pragma unroll
            for (int mf = 0; mf < 4; mf++)
                #pragma unroll
                for (int nf = 0; nf < 4; nf++)
                    mma_f16(acc[mf][nf], af[mf], bf[nf]);
        }
        __syncthreads();
    }
    float* plane = g_dots + ((size_t)(rc*Hh + h))*Nn*Nn;
    #pragma unroll
    for (int mf = 0; mf < 4; mf++) {
        int i = i0 + wm + mf*16 + g;
        #pragma unroll
        for (int nf = 0; nf < 4; nf++) {
            int j = j0 + wn + nf*8 + 2*tig;
            *(float2*)&plane[(size_t)i*Nn + j] =
                make_float2(acc[mf][nf][0]*0.125f, acc[mf][nf][1]*0.125f);
            *(float2*)&plane[(size_t)(i+8)*Nn + j] =
                make_float2(acc[mf][nf][2]*0.125f, acc[mf][nf][3]*0.125f);
        }
    }
}

// ---------------- attention softmax over j (sums RSPLIT planes), half out --------
__global__ void __launch_bounds__(256)
softmax_kernel()
{
    const int row = blockIdx.x;            // h*256 + i
    const int h = row >> 8, i = row & 255, j = threadIdx.x;
    float v = g_bias[((size_t)i*Nn + j)*Hh + h];
    #pragma unroll
    for (int p = 0; p < RSPLIT; p++)
        v += g_dots[(((size_t)(p*Hh + h))*Nn + i)*Nn + j];
    __shared__ float red[8];
    const int lane = j & 31, wid = j >> 5;
    float m = v;
    #pragma unroll
    for (int o = 16; o; o >>= 1) m = fmaxf(m, __shfl_xor_sync(0xffffffffu, m, o));
    if (lane == 0) red[wid] = m;
    __syncthreads();
    float bm = red[0];
    #pragma unroll
    for (int k = 1; k < 8; k++) bm = fmaxf(bm, red[k]);
    __syncthreads();
    float e = __expf(v - bm);
    float s = e;
    #pragma unroll
    for (int o = 16; o; o >>= 1) s += __shfl_xor_sync(0xffffffffu, s, o);
    if (lane == 0) red[wid] = s;
    __syncthreads();
    float su = red[0];
    #pragma unroll
    for (int k = 1; k < 8; k++) su += red[k];
    g_attn[(size_t)row*Nn + j] = __float2half(e/su);
}

// ---------------- attn@V (fp16 MMA): ypre[r,i,h*64+d] = sum_j attn[h,i,j]v[r,j,h,d]
// block: 128(i) x 64(d) per (r,h); warps 4x2, warp tile 32x32; V kept [j][d]
__global__ void __launch_bounds__(256)
attnv_f16_kernel()
{
    __shared__ __half As[128*LDH];   // attn [i][j]
    __shared__ __half Bs[64*LDH];    // v [j][d]
    const int t = threadIdx.x;
    const int i0 = blockIdx.x*128, h = blockIdx.y, r = blockIdx.z;
    const int wid = t >> 5, lane = t & 31;
    const int wm = (wid & 3)*32, wn = (wid >> 2)*32;
    const int g = lane >> 2, tig = lane & 3;
    float acc[2][4][4] = {};

    for (int k0 = 0; k0 < Nn; k0 += 64) {
        #pragma unroll
        for (int u = 0; u < 4; u++) {            // A: 128x64 attn
            int idx = u*256 + t, row = idx >> 3, c8 = (idx & 7)*8;
            *(float4*)&As[row*LDH + c8] =
                *(const float4*)(g_attn + ((size_t)(h*Nn + i0+row))*Nn + k0 + c8);
        }
        #pragma unroll
        for (int u = 0; u < 2; u++) {            // B: 64x64 v (rows j, cols d)
            int idx = u*256 + t, row = idx >> 3, c8 = (idx & 7)*8;
            *(float4*)&Bs[row*LDH + c8] =
                *(const float4*)(g_proj + ((size_t)(r*Nn + k0+row))*PW + 1024 + h*64 + c8);
        }
        __syncthreads();
        #pragma unroll
        for (int ks = 0; ks < 4; ks++) {
            uint32_t af[2][4], bf[4][2];
            #pragma unroll
            for (int mf = 0; mf < 2; mf++) {
                const __half* ap = &As[(wm + mf*16 + g)*LDH + ks*16 + 2*tig];
                af[mf][0] = *(const uint32_t*)ap;
                af[mf][1] = *(const uint32_t*)(ap + 8*LDH);
                af[mf][2] = *(const uint32_t*)(ap + 8);
                af[mf][3] = *(const uint32_t*)(ap + 8*LDH + 8);
            }
            #pragma unroll
            for (int nf = 0; nf < 4; nf++) {
                int n = wn + nf*8 + g;
                const __half* b0p = &Bs[(ks*16 + 2*tig)*LDH + n];
                bf[nf][0] = pack_h2(b0p[0], b0p[LDH]);
                const __half* b1p = b0p + 8*LDH;
                bf[nf][1] = pack_h2(b1p[0], b1p[LDH]);
            }
            #pragma unroll
            for (int mf = 0; mf < 2; mf++)
                #pragma unroll
                for (int nf = 0; nf < 4; nf++)
                    mma_f16(acc[mf][nf], af[mf], bf[nf]);
        }
        __syncthreads();
    }
    #pragma unroll
    for (int mf = 0; mf < 2; mf++) {
        int i = i0 + wm + mf*16 + g;
        #pragma unroll
        for (int nf = 0; nf < 4; nf++) {
            int c = h*64 + wn + nf*8 + 2*tig;
            *(__half2*)&g_ypre[((size_t)(r*Nn) + i)*INNERi + c] =
                __floats2half2_rn(acc[mf][nf][0], acc[mf][nf][1]);
            *(__half2*)&g_ypre[((size_t)(r*Nn) + i + 8)*INNERi + c] =
                __floats2half2_rn(acc[mf][nf][2], acc[mf][nf][3]);
        }
    }
}

// =================================================================================
extern "C" void kernel_launch(void* const* d_in, const int* in_sizes, int n_in,
                              void* d_out, int out_size)
{
    const float* x    = (const float*)d_in[0];
    const float* pair = (const float*)d_in[1];
    const float* wq   = (const float*)d_in[2];
    const float* wkv  = (const float*)d_in[3];
    const float* wo   = (const float*)d_in[4];
    const float* bo   = (const float*)d_in[5];
    const float* png  = (const float*)d_in[6];
    const float* pnb  = (const float*)d_in[7];
    const float* wp   = (const float*)d_in[8];
    const float* swqw = (const float*)d_in[9];
    const float* swqb = (const float*)d_in[10];
    const float* swkw = (const float*)d_in[11];
    const float* swkb = (const float*)d_in[12];
    float* out = (float*)d_out;

    __half *projh, *xh, *WpT, *woT, *ypre;
    float *bp, *qswp;
    cudaGetSymbolAddress((void**)&projh, g_proj);
    cudaGetSymbolAddress((void**)&xh,    g_xh);
    cudaGetSymbolAddress((void**)&WpT,   g_WpT);
    cudaGetSymbolAddress((void**)&woT,   g_woT);
    cudaGetSymbolAddress((void**)&ypre,  g_ypre);
    cudaGetSymbolAddress((void**)&bp,    g_bpack);
    cudaGetSymbolAddress((void**)&qswp,  g_qsw);

    // 1. prep: x -> half, pack W^T (half) + bias + wo^T
    cvtx_kernel<<<(MROWS*Dd/4 + 255)/256, 256>>>(x);
    packw_kernel<<<(PW*Dd + 255)/256, 256>>>(wq, wkv, swkw, swkb, wo);
    // 2. fused projection (fp16): proj = x @ Wpack + bpack  (q|k|v|ksw)
    hgemm_kernel<true><<<dim3(PW/128, MROWS/128), 256>>>(xh, Dd, WpT, Dd, bp, projh, PW, Dd);
    // 3. qsw = x[0] @ swq_w + swq_b  (first MSA row only; tiny, fp32)
    sgemm_kernel<<<dim3(Dd/64, Nn/64), 256>>>(x, swqw, swqb, qswp, Nn, Dd, Dd);
    // 4. soft-tied row weights w[n,h,r]
    seqw_kernel<<<Nn*Hh, 128>>>();
    // 5. pair bias LN + Linear -> [i,j,h]
    pairbias_kernel<<<Nn*Nn/8, 256>>>(pair, png, pnb, wp);
    // 6. tied dots (fp16, RSPLIT partial planes)
    dots_f16_kernel<<<dim3(Nn/128, Nn/128, RSPLIT*Hh), 256>>>();
    // 7. attention softmax (sum planes + bias), half out
    softmax_kernel<<<Hh*Nn, 256>>>();
    // 8. ypre = attn @ V  (fp16), written as (r,i,h*64+d)
    attnv_f16_kernel<<<dim3(Nn/128, Hh, Rr), 256>>>();
    // 9. final projection (fp16): out = ypre @ wo + bo
    hgemm_kernel<false><<<dim3(Dd/128, MROWS/128), 256>>>(ypre, INNERi, woT, INNERi, bo, out, Dd, INNERi);
}

// round 5
// speedup vs baseline: 5.7414x; 1.1779x over previous
#include <cuda_runtime.h>
#include <cuda_fp16.h>
#include <cstdint>

// Problem constants (fixed by setup_inputs)
#define Rr      128
#define Nn      256
#define Dd      128
#define Hh      8
#define DHh     64
#define INNERi  512
#define MROWS   (Rr*Nn)      // 32768
#define PW      1664         // packed proj cols: 512 q | 512 k | 512 v | 128 ksw
#define RSPLIT  8            // dots r-split planes
#define LDH     72           // smem half pitch (dots/attnv A tiles)
#define LDK     40           // hgemm k-slab pitch (32 + 8 pad)
#define LDVT    74           // attnv transposed-V pitch (even, conflict-reduced)

// ---------------- scratch (static device globals; no allocation) ----------------
__device__ __half g_proj [(size_t)MROWS*PW];     // 109 MB: q|k|v|ksw (half)
__device__ __half g_xh   [(size_t)MROWS*Dd];     // x in half
__device__ __half g_WpT  [(size_t)PW*Dd];        // packed proj weights, [n][k] half
__device__ float  g_bpack[PW];
__device__ __half g_woT  [Dd*INNERi];            // wo^T [n][k] half
__device__ float  g_qsw  [Nn*Dd];
__device__ float  g_w    [Nn*Hh*Rr];             // softmaxed row weights [n][h][r]
__device__ float  g_dots [(size_t)RSPLIT*Hh*Nn*Nn];
__device__ float  g_bias [Nn*Nn*Hh];             // pair bias -> heads [i][j][h]
__device__ __half g_attn [Hh*Nn*Nn];
__device__ __half g_ypre [(size_t)MROWS*INNERi]; // 32 MB

// ---------------- helpers --------------------------------------------------------
__device__ __forceinline__ void mma_f16(float* d, const uint32_t* a, const uint32_t* b) {
    asm volatile(
        "mma.sync.aligned.m16n8k16.row.col.f32.f16.f16.f32 "
        "{%0,%1,%2,%3}, {%4,%5,%6,%7}, {%8,%9}, {%0,%1,%2,%3};"
        : "+f"(d[0]), "+f"(d[1]), "+f"(d[2]), "+f"(d[3])
        : "r"(a[0]), "r"(a[1]), "r"(a[2]), "r"(a[3]), "r"(b[0]), "r"(b[1]));
}

__device__ __forceinline__ void cp16(void* smem, const void* gmem) {
    uint32_t s = (uint32_t)__cvta_generic_to_shared(smem);
    asm volatile("cp.async.cg.shared.global [%0], [%1], 16;\n" :: "r"(s), "l"(gmem));
}
#define CP_COMMIT() asm volatile("cp.async.commit_group;\n")
#define CP_WAIT1()  asm volatile("cp.async.wait_group 1;\n")

// ---------------- prep: convert x to half ----------------------------------------
__global__ void cvtx_kernel(const float* __restrict__ x)
{
    int i4 = (blockIdx.x*blockDim.x + threadIdx.x) * 4;
    if (i4 < MROWS*Dd) {
        float4 v = *(const float4*)&x[i4];
        __half2* p = (__half2*)&g_xh[i4];
        p[0] = __floats2half2_rn(v.x, v.y);
        p[1] = __floats2half2_rn(v.z, v.w);
    }
}

// ---------------- prep: pack weights ---------------------------------------------
__global__ void packw_kernel(const float* __restrict__ wq,
                             const float* __restrict__ wkv,
                             const float* __restrict__ swkw,
                             const float* __restrict__ swkb,
                             const float* __restrict__ wo)
{
    int idx = blockIdx.x*blockDim.x + threadIdx.x;
    if (idx < PW*Dd) {
        int c = idx >> 7, k = idx & 127;
        float v;
        if      (c < 512)  v = wq  [k*512  + c];
        else if (c < 1536) v = wkv [k*1024 + (c-512)];
        else               v = swkw[k*Dd   + (c-1536)];
        g_WpT[idx] = __float2half(v);
    }
    if (idx < Dd*INNERi) {
        int n = idx >> 9, k = idx & 511;
        g_woT[idx] = __float2half(wo[k*Dd + n]);
    }
    if (idx < PW) g_bpack[idx] = (idx < 1536) ? 0.f : swkb[idx-1536];
}

// ---------------- pipelined fp16 GEMM: C[M,N] = A[M,K] @ Bt[N,K]^T + bias --------
// block 128x128, 8 warps (2x4), warp tile 64x32, k-slab 32, cp.async 2-stage
template<bool OUTH>
__global__ void __launch_bounds__(256)
hgemm_kernel(const __half* __restrict__ A, int lda,
             const __half* __restrict__ Bt, int ldb,
             const float* __restrict__ bias,
             void* __restrict__ Cv, int ldc, int K)
{
    __shared__ __half As[2][128*LDK];
    __shared__ __half Bs[2][128*LDK];
    const int t = threadIdx.x;
    const int m0 = blockIdx.y*128, n0 = blockIdx.x*128;
    const int wid = t >> 5, lane = t & 31;
    const int wm = (wid & 1)*64, wn = (wid >> 1)*32;
    const int g = lane >> 2, tig = lane & 3;
    const int lrow = t >> 2, lc8 = (t & 3)*8;       // tile-load mapping (2 rows/thread)
    float acc[4][4][4] = {};

    const int NT = K >> 5;
    // prologue: stage 0
    #pragma unroll
    for (int u = 0; u < 2; u++) {
        int row = u*64 + lrow;
        cp16(&As[0][row*LDK + lc8], &A[(size_t)(m0+row)*lda + lc8]);
        cp16(&Bs[0][row*LDK + lc8], &Bt[(size_t)(n0+row)*ldb + lc8]);
    }
    CP_COMMIT();

    for (int kt = 0; kt < NT; kt++) {
        if (kt + 1 < NT) {
            int k0 = (kt+1) << 5, s = (kt+1) & 1;
            #pragma unroll
            for (int u = 0; u < 2; u++) {
                int row = u*64 + lrow;
                cp16(&As[s][row*LDK + lc8], &A[(size_t)(m0+row)*lda + k0 + lc8]);
                cp16(&Bs[s][row*LDK + lc8], &Bt[(size_t)(n0+row)*ldb + k0 + lc8]);
            }
        }
        CP_COMMIT();
        CP_WAIT1();
        __syncthreads();
        const __half* Ac = As[kt & 1];
        const __half* Bc = Bs[kt & 1];
        #pragma unroll
        for (int ks = 0; ks < 2; ks++) {
            uint32_t af[4][4], bf[4][2];
            #pragma unroll
            for (int mf = 0; mf < 4; mf++) {
                const __half* ap = &Ac[(wm + mf*16 + g)*LDK + ks*16 + 2*tig];
                af[mf][0] = *(const uint32_t*)ap;
                af[mf][1] = *(const uint32_t*)(ap + 8*LDK);
                af[mf][2] = *(const uint32_t*)(ap + 8);
                af[mf][3] = *(const uint32_t*)(ap + 8*LDK + 8);
            }
            #pragma unroll
            for (int nf = 0; nf < 4; nf++) {
                const __half* bp = &Bc[(wn + nf*8 + g)*LDK + ks*16 + 2*tig];
                bf[nf][0] = *(const uint32_t*)bp;
                bf[nf][1] = *(const uint32_t*)(bp + 8);
            }
            #pragma unroll
            for (int mf = 0; mf < 4; mf++)
                #pragma unroll
                for (int nf = 0; nf < 4; nf++)
                    mma_f16(acc[mf][nf], af[mf], bf[nf]);
        }
        __syncthreads();
    }
    #pragma unroll
    for (int mf = 0; mf < 4; mf++) {
        int r0 = m0 + wm + mf*16 + g;
        #pragma unroll
        for (int nf = 0; nf < 4; nf++) {
            int c = n0 + wn + nf*8 + 2*tig;
            float b0 = 0.f, b1 = 0.f;
            if (bias) { b0 = bias[c]; b1 = bias[c+1]; }
            if (OUTH) {
                __half* C = (__half*)Cv;
                *(__half2*)&C[(size_t)r0*ldc + c] =
                    __floats2half2_rn(acc[mf][nf][0]+b0, acc[mf][nf][1]+b1);
                *(__half2*)&C[(size_t)(r0+8)*ldc + c] =
                    __floats2half2_rn(acc[mf][nf][2]+b0, acc[mf][nf][3]+b1);
            } else {
                float* C = (float*)Cv;
                *(float2*)&C[(size_t)r0*ldc + c] =
                    make_float2(acc[mf][nf][0]+b0, acc[mf][nf][1]+b1);
                *(float2*)&C[(size_t)(r0+8)*ldc + c] =
                    make_float2(acc[mf][nf][2]+b0, acc[mf][nf][3]+b1);
            }
        }
    }
}

// ---------------- qsw: out[n][c] = x[0,n,:] . swq_w[:,c] + swq_b[c] --------------
// one block per n (256 blocks), thread c
__global__ void __launch_bounds__(128)
qsw_kernel(const float* __restrict__ x, const float* __restrict__ swqw,
           const float* __restrict__ swqb)
{
    const int n = blockIdx.x, c = threadIdx.x;
    __shared__ float xs[Dd];
    xs[c] = x[n*Dd + c];
    __syncthreads();
    float acc = 0.f;
    #pragma unroll 8
    for (int k = 0; k < Dd; k++) acc += xs[k]*swqw[k*Dd + c];
    g_qsw[n*Dd + c] = acc + swqb[c];
}

// ---------------- seq-weight: block per n; thread r reads contiguous ksw row -----
__global__ void __launch_bounds__(128)
seqw_kernel()
{
    const int n = blockIdx.x, r = threadIdx.x;
    __shared__ float qs[Dd];
    __shared__ float sm[Hh][132];
    __shared__ float smax[Hh], ssum[Hh];
    if (r < Dd) qs[r] = g_qsw[n*Dd + r];
    // also second half loaded by... blockDim=128 covers Dd=128 exactly
    __syncthreads();

    // 8 head logits; ksw row (128 halves, contiguous 256B)
    const __half* kp = g_proj + ((size_t)(r*Nn + n))*PW + 1536;
    float sh[Hh] = {};
    #pragma unroll
    for (int q8 = 0; q8 < 16; q8++) {          // 16 chunks of 8 halves
        float4 raw = *(const float4*)(kp + q8*8);
        const __half2* h2 = (const __half2*)&raw;
        int h = q8 >> 1, d0 = (q8 & 1)*8;
        #pragma unroll
        for (int p = 0; p < 4; p++) {
            float2 f = __half22float2(h2[p]);
            sh[h] += qs[h*16 + d0 + 2*p]*f.x + qs[h*16 + d0 + 2*p + 1]*f.y;
        }
    }
    #pragma unroll
    for (int h = 0; h < Hh; h++) { sh[h] *= 0.25f; sm[h][r] = sh[h]; }
    __syncthreads();

    // warps 0-3 compute per-head max (2 heads each)
    const int wid = r >> 5, lane = r & 31;
    #pragma unroll
    for (int hh = 0; hh < 2; hh++) {
        int h = wid*2 + hh;
        float m = fmaxf(fmaxf(sm[h][lane], sm[h][lane+32]),
                        fmaxf(sm[h][lane+64], sm[h][lane+96]));
        #pragma unroll
        for (int o = 16; o; o >>= 1) m = fmaxf(m, __shfl_xor_sync(0xffffffffu, m, o));
        if (lane == 0) smax[h] = m;
    }
    __syncthreads();
    float e[Hh];
    #pragma unroll
    for (int h = 0; h < Hh; h++) { e[h] = __expf(sh[h] - smax[h]); sm[h][r] = e[h]; }
    __syncthreads();
    #pragma unroll
    for (int hh = 0; hh < 2; hh++) {
        int h = wid*2 + hh;
        float s = sm[h][lane] + sm[h][lane+32] + sm[h][lane+64] + sm[h][lane+96];
        #pragma unroll
        for (int o = 16; o; o >>= 1) s += __shfl_xor_sync(0xffffffffu, s, o);
        if (lane == 0) ssum[h] = s;
    }
    __syncthreads();
    #pragma unroll
    for (int h = 0; h < Hh; h++)
        g_w[(n*Hh + h)*Rr + r] = e[h] / ssum[h];
}

// ---------------- pair bias: per-(i,j) LayerNorm + Linear(128->8) ----------------
__global__ void __launch_bounds__(256)
pairbias_kernel(const float* __restrict__ pb, const float* __restrict__ gg,
                const float* __restrict__ bb, const float* __restrict__ wp)
{
    __shared__ float s_wp[Dd*Hh];
    __shared__ float s_g[Dd], s_b[Dd];
    const int t = threadIdx.x;
    for (int k = t; k < Dd*Hh; k += 256) s_wp[k] = wp[k];
    if (t < Dd) { s_g[t] = gg[t]; s_b[t] = bb[t]; }
    __syncthreads();
    const int warp = t >> 5, lane = t & 31;
    const int p = blockIdx.x*8 + warp;
    const float* rowp = pb + (size_t)p*Dd;
    float v[4];
    #pragma unroll
    for (int u = 0; u < 4; u++) v[u] = rowp[lane + 32*u];
    float s = v[0]+v[1]+v[2]+v[3];
    #pragma unroll
    for (int o = 16; o; o >>= 1) s += __shfl_xor_sync(0xffffffffu, s, o);
    const float mu = s * (1.f/128.f);
    float q = 0.f;
    #pragma unroll
    for (int u = 0; u < 4; u++) { float d = v[u]-mu; q += d*d; }
    #pragma unroll
    for (int o = 16; o; o >>= 1) q += __shfl_xor_sync(0xffffffffu, q, o);
    const float rstd = rsqrtf(q*(1.f/128.f) + 1e-5f);
    float acc[8] = {};
    #pragma unroll
    for (int u = 0; u < 4; u++) {
        int c = lane + 32*u;
        float ln = (v[u]-mu)*rstd*s_g[c] + s_b[c];
        #pragma unroll
        for (int h = 0; h < 8; h++) acc[h] += ln*s_wp[c*8 + h];
    }
    #pragma unroll
    for (int h = 0; h < 8; h++)
        #pragma unroll
        for (int o = 16; o; o >>= 1) acc[h] += __shfl_xor_sync(0xffffffffu, acc[h], o);
    float outv = 0.f;
    #pragma unroll
    for (int h = 0; h < 8; h++) if (lane == h) outv = acc[h];
    if (lane < 8) g_bias[(size_t)p*8 + lane] = outv;
}

// ---------------- tied dots (fp16 MMA, register-prefetch pipeline) ---------------
__global__ void __launch_bounds__(256)
dots_f16_kernel()
{
    __shared__ __half Qs[128*LDH];
    __shared__ __half Ks[128*LDH];
    const int t = threadIdx.x;
    const int j0 = blockIdx.x*128, i0 = blockIdx.y*128;
    const int h = blockIdx.z & 7, rc = blockIdx.z >> 3;
    const int wid = t >> 5, lane = t & 31;
    const int wm = (wid & 1)*64, wn = (wid >> 1)*32;
    const int g = lane >> 2, tig = lane & 3;
    const int rowb = t >> 3, c8 = (t & 7)*8;
    float acc[4][4][4] = {};
    float4 q4[4], k4[4]; float sc[4];

    const int rbeg = rc*(Rr/RSPLIT), rend = rbeg + Rr/RSPLIT;

    // prologue load
    #pragma unroll
    for (int u = 0; u < 4; u++) {
        int row = u*32 + rowb;
        q4[u] = *(const float4*)(g_proj + ((size_t)(rbeg*Nn + i0+row))*PW + h*64 + c8);
        k4[u] = *(const float4*)(g_proj + ((size_t)(rbeg*Nn + j0+row))*PW + 512 + h*64 + c8);
        sc[u] = g_w[((i0+row)*Hh + h)*Rr + rbeg];
    }

    for (int r = rbeg; r < rend; ++r) {
        // store staged tiles (scale Q rows by w)
        #pragma unroll
        for (int u = 0; u < 4; u++) {
            int row = u*32 + rowb;
            float4 a = q4[u];
            __half2 sc2 = __float2half2_rn(sc[u]);
            __half2* ah = (__half2*)&a;
            ah[0] = __hmul2(ah[0], sc2); ah[1] = __hmul2(ah[1], sc2);
            ah[2] = __hmul2(ah[2], sc2); ah[3] = __hmul2(ah[3], sc2);
            *(float4*)&Qs[row*LDH + c8] = a;
            *(float4*)&Ks[row*LDH + c8] = k4[u];
        }
        __syncthreads();
        // prefetch next r while MMAs run
        if (r + 1 < rend) {
            #pragma unroll
            for (int u = 0; u < 4; u++) {
                int row = u*32 + rowb;
                q4[u] = *(const float4*)(g_proj + ((size_t)((r+1)*Nn + i0+row))*PW + h*64 + c8);
                k4[u] = *(const float4*)(g_proj + ((size_t)((r+1)*Nn + j0+row))*PW + 512 + h*64 + c8);
                sc[u] = g_w[((i0+row)*Hh + h)*Rr + r+1];
            }
        }
        #pragma unroll
        for (int ks = 0; ks < 4; ks++) {
            uint32_t af[4][4], bf[4][2];
            #pragma unroll
            for (int mf = 0; mf < 4; mf++) {
                const __half* ap = &Qs[(wm + mf*16 + g)*LDH + ks*16 + 2*tig];
                af[mf][0] = *(const uint32_t*)ap;
                af[mf][1] = *(const uint32_t*)(ap + 8*LDH);
                af[mf][2] = *(const uint32_t*)(ap + 8);
                af[mf][3] = *(const uint32_t*)(ap + 8*LDH + 8);
            }
            #pragma unroll
            for (int nf = 0; nf < 4; nf++) {
                const __half* bp = &Ks[(wn + nf*8 + g)*LDH + ks*16 + 2*tig];
                bf[nf][0] = *(const uint32_t*)bp;
                bf[nf][1] = *(const uint32_t*)(bp + 8);
            }
            #pragma unroll
            for (int mf = 0; mf < 4; mf++)
                #pragma unroll
                for (int nf = 0; nf < 4; nf++)
                    mma_f16(acc[mf][nf], af[mf], bf[nf]);
        }
        __syncthreads();
    }
    float* plane = g_dots + ((size_t)(rc*Hh + h))*Nn*Nn;
    #pragma unroll
    for (int mf = 0; mf < 4; mf++) {
        int i = i0 + wm + mf*16 + g;
        #pragma unroll
        for (int nf = 0; nf < 4; nf++) {
            int j = j0 + wn + nf*8 + 2*tig;
            *(float2*)&plane[(size_t)i*Nn + j] =
                make_float2(acc[mf][nf][0]*0.125f, acc[mf][nf][1]*0.125f);
            *(float2*)&plane[(size_t)(i+8)*Nn + j] =
                make_float2(acc[mf][nf][2]*0.125f, acc[mf][nf][3]*0.125f);
        }
    }
}

// ---------------- attention softmax over j (sums RSPLIT planes), half out --------
__global__ void __launch_bounds__(256)
softmax_kernel()
{
    const int row = blockIdx.x;            // h*256 + i
    const int h = row >> 8, i = row & 255, j = threadIdx.x;
    float v = g_bias[((size_t)i*Nn + j)*Hh + h];
    #pragma unroll
    for (int p = 0; p < RSPLIT; p++)
        v += g_dots[(((size_t)(p*Hh + h))*Nn + i)*Nn + j];
    __shared__ float red[8];
    const int lane = j & 31, wid = j >> 5;
    float m = v;
    #pragma unroll
    for (int o = 16; o; o >>= 1) m = fmaxf(m, __shfl_xor_sync(0xffffffffu, m, o));
    if (lane == 0) red[wid] = m;
    __syncthreads();
    float bm = red[0];
    #pragma unroll
    for (int k = 1; k < 8; k++) bm = fmaxf(bm, red[k]);
    __syncthreads();
    float e = __expf(v - bm);
    float s = e;
    #pragma unroll
    for (int o = 16; o; o >>= 1) s += __shfl_xor_sync(0xffffffffu, s, o);
    if (lane == 0) red[wid] = s;
    __syncthreads();
    float su = red[0];
    #pragma unroll
    for (int k = 1; k < 8; k++) su += red[k];
    g_attn[(size_t)row*Nn + j] = __float2half(e/su);
}

// ---------------- attn@V (fp16 MMA): ypre[r,i,h*64+d] = sum_j attn[h,i,j]v[r,j,h,d]
// transposed V in smem (aligned fragment loads) + register prefetch
__global__ void __launch_bounds__(256)
attnv_f16_kernel()
{
    __shared__ __half As[128*LDH];    // attn [i][j]
    __shared__ __half BsT[64*LDVT];   // v^T [d][j]
    const int t = threadIdx.x;
    const int i0 = blockIdx.x*128, h = blockIdx.y, r = blockIdx.z;
    const int wid = t >> 5, lane = t & 31;
    const int wm = (wid & 3)*32, wn = (wid >> 2)*32;
    const int g = lane >> 2, tig = lane & 3;
    const int rowb = t >> 3, c8 = (t & 7)*8;
    float acc[2][4][4] = {};
    float4 a4[4], b4[2];

    // prologue load (k0 = 0)
    #pragma unroll
    for (int u = 0; u < 4; u++)
        a4[u] = *(const float4*)(g_attn + ((size_t)(h*Nn + i0 + u*32+rowb))*Nn + c8);
    #pragma unroll
    for (int u = 0; u < 2; u++)
        b4[u] = *(const float4*)(g_proj + ((size_t)(r*Nn + u*32+rowb))*PW + 1024 + h*64 + c8);

    for (int kt = 0; kt < 4; kt++) {
        // store staged tiles: A direct, V transposed
        #pragma unroll
        for (int u = 0; u < 4; u++)
            *(float4*)&As[(u*32+rowb)*LDH + c8] = a4[u];
        #pragma unroll
        for (int u = 0; u < 2; u++) {
            const __half* hp = (const __half*)&b4[u];
            int j = u*32 + rowb;
            #pragma unroll
            for (int e = 0; e < 8; e++)
                BsT[(c8 + e)*LDVT + j] = hp[e];
        }
        __syncthreads();
        // prefetch next slab
        if (kt < 3) {
            int k0 = (kt+1)*64;
            #pragma unroll
            for (int u = 0; u < 4; u++)
                a4[u] = *(const float4*)(g_attn + ((size_t)(h*Nn + i0 + u*32+rowb))*Nn + k0 + c8);
            #pragma unroll
            for (int u = 0; u < 2; u++)
                b4[u] = *(const float4*)(g_proj + ((size_t)(r*Nn + k0 + u*32+rowb))*PW + 1024 + h*64 + c8);
        }
        #pragma unroll
        for (int ks = 0; ks < 4; ks++) {
            uint32_t af[2][4], bf[4][2];
            #pragma unroll
            for (int mf = 0; mf < 2; mf++) {
                const __half* ap = &As[(wm + mf*16 + g)*LDH + ks*16 + 2*tig];
                af[mf][0] = *(const uint32_t*)ap;
                af[mf][1] = *(const uint32_t*)(ap + 8*LDH);
                af[mf][2] = *(const uint32_t*)(ap + 8);
                af[mf][3] = *(const uint32_t*)(ap + 8*LDH + 8);
            }
            #pragma unroll
            for (int nf = 0; nf < 4; nf++) {
                const __half* bp = &BsT[(wn + nf*8 + g)*LDVT + ks*16 + 2*tig];
                bf[nf][0] = *(const uint32_t*)bp;
                bf[nf][1] = *(const uint32_t*)(bp + 8);
            }
            #pragma unroll
            for (int mf = 0; mf < 2; mf++)
                #pragma unroll
                for (int nf = 0; nf < 4; nf++)
                    mma_f16(acc[mf][nf], af[mf], bf[nf]);
        }
        __syncthreads();
    }
    #pragma unroll
    for (int mf = 0; mf < 2; mf++) {
        int i = i0 + wm + mf*16 + g;
        #pragma unroll
        for (int nf = 0; nf < 4; nf++) {
            int c = h*64 + wn + nf*8 + 2*tig;
            *(__half2*)&g_ypre[((size_t)(r*Nn) + i)*INNERi + c] =
                __floats2half2_rn(acc[mf][nf][0], acc[mf][nf][1]);
            *(__half2*)&g_ypre[((size_t)(r*Nn) + i + 8)*INNERi + c] =
                __floats2half2_rn(acc[mf][nf][2], acc[mf][nf][3]);
        }
    }
}

// =================================================================================
extern "C" void kernel_launch(void* const* d_in, const int* in_sizes, int n_in,
                              void* d_out, int out_size)
{
    const float* x    = (const float*)d_in[0];
    const float* pair = (const float*)d_in[1];
    const float* wq   = (const float*)d_in[2];
    const float* wkv  = (const float*)d_in[3];
    const float* wo   = (const float*)d_in[4];
    const float* bo   = (const float*)d_in[5];
    const float* png  = (const float*)d_in[6];
    const float* pnb  = (const float*)d_in[7];
    const float* wp   = (const float*)d_in[8];
    const float* swqw = (const float*)d_in[9];
    const float* swqb = (const float*)d_in[10];
    const float* swkw = (const float*)d_in[11];
    const float* swkb = (const float*)d_in[12];
    float* out = (float*)d_out;

    __half *projh, *xh, *WpT, *woT, *ypre;
    float *bp;
    cudaGetSymbolAddress((void**)&projh, g_proj);
    cudaGetSymbolAddress((void**)&xh,    g_xh);
    cudaGetSymbolAddress((void**)&WpT,   g_WpT);
    cudaGetSymbolAddress((void**)&woT,   g_woT);
    cudaGetSymbolAddress((void**)&ypre,  g_ypre);
    cudaGetSymbolAddress((void**)&bp,    g_bpack);

    // 1. prep: x -> half, pack W^T (half) + bias + wo^T
    cvtx_kernel<<<(MROWS*Dd/4 + 255)/256, 256>>>(x);
    packw_kernel<<<(PW*Dd + 255)/256, 256>>>(wq, wkv, swkw, swkb, wo);
    // 2. fused projection (fp16, pipelined): proj = x @ Wpack + bpack  (q|k|v|ksw)
    hgemm_kernel<true><<<dim3(PW/128, MROWS/128), 256>>>(xh, Dd, WpT, Dd, bp, projh, PW, Dd);
    // 3. qsw = x[0] @ swq_w + swq_b
    qsw_kernel<<<Nn, 128>>>(x, swqw, swqb);
    // 4. soft-tied row weights w[n,h,r] (contiguous ksw reads)
    seqw_kernel<<<Nn, 128>>>();
    // 5. pair bias LN + Linear -> [i,j,h]
    pairbias_kernel<<<Nn*Nn/8, 256>>>(pair, png, pnb, wp);
    // 6. tied dots (fp16, RSPLIT planes, register-prefetch)
    dots_f16_kernel<<<dim3(Nn/128, Nn/128, RSPLIT*Hh), 256>>>();
    // 7. attention softmax (sum planes + bias), half out
    softmax_kernel<<<Hh*Nn, 256>>>();
    // 8. ypre = attn @ V  (fp16, transposed-V smem), written as (r,i,h*64+d)
    attnv_f16_kernel<<<dim3(Nn/128, Hh, Rr), 256>>>();
    // 9. final projection (fp16, pipelined): out = ypre @ wo + bo
    hgemm_kernel<false><<<dim3(Dd/128, MROWS/128), 256>>>(ypre, INNERi, woT, INNERi, bo, out, Dd, INNERi);
}